// round 2
// baseline (speedup 1.0000x reference)
#include <cuda_runtime.h>
#include <cstdint>

#define NN 50000
#define EE 625000
#define D0 128
#define D1 128
#define D2 64

// ---- device-global scratch (no allocation allowed) ----
__device__ int   g_degi[NN];
__device__ float g_dinv[NN];
__device__ int   g_off [NN + 1];
__device__ int   g_cur [NN];
__device__ int   g_src [EE];
__device__ float g_coef[EE];
__device__ float g_h1  [(size_t)NN * D1];
__device__ float g_agg1[(size_t)NN * D1];
__device__ float g_h2  [(size_t)NN * D2];

// ---------------------------------------------------------------------------
// Degree / normalization / CSR build
// ---------------------------------------------------------------------------
__global__ void k_zero_deg(int n) {
    int i = blockIdx.x * blockDim.x + threadIdx.x;
    if (i < n) g_degi[i] = 0;
}

__global__ void k_count_deg(const int* __restrict__ ei, int E) {
    int e = blockIdx.x * blockDim.x + threadIdx.x;
    if (e < E) atomicAdd(&g_degi[ei[E + e]], 1);
}

__global__ void k_dinv(int n) {
    int i = blockIdx.x * blockDim.x + threadIdx.x;
    if (i < n) g_dinv[i] = rsqrtf((float)(g_degi[i] + 1));   // +1 self-loop
}

// single-block exclusive scan of g_degi -> g_off (and g_cur copy)
__global__ void k_scan(int N, int E) {
    __shared__ int ssum[1024];
    int t = threadIdx.x;
    int C = (N + 1023) / 1024;
    int b = t * C, e = min(b + C, N);
    int s = 0;
    for (int i = b; i < e; i++) s += g_degi[i];
    ssum[t] = s;
    __syncthreads();
    // Hillis-Steele inclusive scan
    for (int off = 1; off < 1024; off <<= 1) {
        int v = (t >= off) ? ssum[t - off] : 0;
        __syncthreads();
        ssum[t] += v;
        __syncthreads();
    }
    int ex = (t == 0) ? 0 : ssum[t - 1];
    for (int i = b; i < e; i++) {
        g_off[i] = ex;
        g_cur[i] = ex;
        ex += g_degi[i];
    }
    if (t == 1023) g_off[N] = E;
}

__global__ void k_fill(const int* __restrict__ ei, int E) {
    int e = blockIdx.x * blockDim.x + threadIdx.x;
    if (e >= E) return;
    int s = __ldg(ei + e);
    int d = __ldg(ei + E + e);
    int p = atomicAdd(&g_cur[d], 1);
    g_src[p]  = s;
    g_coef[p] = g_dinv[s] * g_dinv[d];
}

// ---------------------------------------------------------------------------
// Register-blocked fp32 GEMM: OUT[row][c] = sum_k A'[row][k] * W[c][k]
//   A' = relu(A + bin) if IN_ACT
//   H   <- acc                        (pre-norm, needed by gather)
//   AGG <- dinv[row]^2 * acc (+bout)  (self-loop term, bias folded)
// 128x128 tile, 256 threads, 8 rows x (NG*4) cols per thread.
// smem tiles stored k-major with xor swizzle to kill STS bank conflicts while
// keeping the hot-loop LDS.128 conflict-free.
// ---------------------------------------------------------------------------
template <int NOUT, bool IN_ACT, bool OUT_BIAS>
__global__ __launch_bounds__(256, 1)
void k_gemm(const float* __restrict__ A, const float* __restrict__ W,
            const float* __restrict__ bin, const float* __restrict__ bout,
            float* __restrict__ H, float* __restrict__ AGG, int M)
{
    constexpr int K  = 128, TM = 128;
    constexpr int WS = NOUT + 4;       // smem row stride (floats), W tile
    constexpr int XS = TM + 4;         // smem row stride, X tile
    constexpr int NG = NOUT / 64;      // col groups per thread (2 or 1)
    constexpr int WM = NOUT / 4 - 1;   // swizzle mask W (31 or 15)
    constexpr int XM = TM / 4 - 1;     // swizzle mask X (31)

    extern __shared__ float sm[];
    float* Ws = sm;                    // [K][WS] swizzled
    float* Xs = sm + K * WS;           // [K][XS] swizzled

    const int tid  = threadIdx.x;
    const int row0 = blockIdx.x * TM;

    // ---- W -> smem, transposed: element (k, c) at k*WS + 4*((c>>2)^(k&WM)) + (c&3)
    for (int fid = tid; fid < NOUT * (K / 4); fid += 256) {
        int c  = fid >> 5;
        int kq = fid & 31;
        float4 w = *reinterpret_cast<const float4*>(W + (size_t)c * K + kq * 4);
        float wr[4] = {w.x, w.y, w.z, w.w};
        #pragma unroll
        for (int u = 0; u < 4; u++) {
            int k = kq * 4 + u;
            Ws[k * WS + 4 * (((c >> 2) ^ (k & WM))) + (c & 3)] = wr[u];
        }
    }

    // ---- X -> smem, transposed (+ optional relu(x+bin))
    for (int fid = tid; fid < TM * (K / 4); fid += 256) {
        int r   = fid >> 5;
        int kq  = fid & 31;
        int row = row0 + r;
        float4 v = make_float4(0.f, 0.f, 0.f, 0.f);
        if (row < M)
            v = *reinterpret_cast<const float4*>(A + (size_t)row * K + kq * 4);
        if (IN_ACT) {
            v.x = fmaxf(v.x + __ldg(bin + kq * 4 + 0), 0.f);
            v.y = fmaxf(v.y + __ldg(bin + kq * 4 + 1), 0.f);
            v.z = fmaxf(v.z + __ldg(bin + kq * 4 + 2), 0.f);
            v.w = fmaxf(v.w + __ldg(bin + kq * 4 + 3), 0.f);
        }
        float xr[4] = {v.x, v.y, v.z, v.w};
        #pragma unroll
        for (int u = 0; u < 4; u++) {
            int k = kq * 4 + u;
            Xs[k * XS + 4 * (((r >> 2) ^ (k & XM))) + (r & 3)] = xr[u];
        }
    }
    __syncthreads();

    const int tx = tid & 15;           // col threads
    const int ty = tid >> 4;           // row threads

    float acc[2][4][NG][4];
    #pragma unroll
    for (int h = 0; h < 2; h++)
        #pragma unroll
        for (int i = 0; i < 4; i++)
            #pragma unroll
            for (int g = 0; g < NG; g++)
                #pragma unroll
                for (int j = 0; j < 4; j++) acc[h][i][g][j] = 0.f;

    #pragma unroll 4
    for (int k = 0; k < K; k++) {
        const int kx = k & XM;
        const int kw = k & WM;
        float4 xv[2];
        xv[0] = *reinterpret_cast<const float4*>(&Xs[k * XS + 4 * (ty ^ kx)]);
        xv[1] = *reinterpret_cast<const float4*>(&Xs[k * XS + 4 * ((ty + 16) ^ kx)]);
        float4 wv[NG];
        #pragma unroll
        for (int g = 0; g < NG; g++)
            wv[g] = *reinterpret_cast<const float4*>(&Ws[k * WS + 4 * ((tx + 16 * g) ^ kw)]);

        #pragma unroll
        for (int h = 0; h < 2; h++) {
            float xr[4] = {xv[h].x, xv[h].y, xv[h].z, xv[h].w};
            #pragma unroll
            for (int i = 0; i < 4; i++)
                #pragma unroll
                for (int g = 0; g < NG; g++) {
                    acc[h][i][g][0] = fmaf(xr[i], wv[g].x, acc[h][i][g][0]);
                    acc[h][i][g][1] = fmaf(xr[i], wv[g].y, acc[h][i][g][1]);
                    acc[h][i][g][2] = fmaf(xr[i], wv[g].z, acc[h][i][g][2]);
                    acc[h][i][g][3] = fmaf(xr[i], wv[g].w, acc[h][i][g][3]);
                }
        }
    }

    // ---- epilogue
    #pragma unroll
    for (int h = 0; h < 2; h++)
        #pragma unroll
        for (int i = 0; i < 4; i++) {
            int row = row0 + ty * 4 + h * 64 + i;
            if (row < M) {
                float s = g_dinv[row];
                s = s * s;
                #pragma unroll
                for (int g = 0; g < NG; g++) {
                    int c = tx * 4 + g * 64;
                    float4 hv = make_float4(acc[h][i][g][0], acc[h][i][g][1],
                                            acc[h][i][g][2], acc[h][i][g][3]);
                    *reinterpret_cast<float4*>(H + (size_t)row * NOUT + c) = hv;
                    float4 av;
                    if (OUT_BIAS) {
                        av.x = fmaf(s, hv.x, __ldg(bout + c + 0));
                        av.y = fmaf(s, hv.y, __ldg(bout + c + 1));
                        av.z = fmaf(s, hv.z, __ldg(bout + c + 2));
                        av.w = fmaf(s, hv.w, __ldg(bout + c + 3));
                    } else {
                        av = make_float4(s * hv.x, s * hv.y, s * hv.z, s * hv.w);
                    }
                    *reinterpret_cast<float4*>(AGG + (size_t)row * NOUT + c) = av;
                }
            }
        }
}

// ---------------------------------------------------------------------------
// CSR gather: AGG[n] += sum_{j in csr(n)} coef[j] * H[src[j]]   (no atomics)
// d=128: one warp per node, lane -> float4
// ---------------------------------------------------------------------------
__global__ void k_gather128(const float* __restrict__ H, float* __restrict__ AGG, int N)
{
    int node = blockIdx.x * (blockDim.x >> 5) + (threadIdx.x >> 5);
    int lane = threadIdx.x & 31;
    if (node >= N) return;
    int beg = g_off[node], end = g_off[node + 1];
    float* p = AGG + (size_t)node * 128 + lane * 4;
    float4 a0 = *reinterpret_cast<const float4*>(p);   // self-loop term (from GEMM)
    float4 a1 = make_float4(0.f, 0.f, 0.f, 0.f);
    int j = beg;
    for (; j + 1 < end; j += 2) {
        int   s0 = __ldg(g_src  + j),     s1 = __ldg(g_src  + j + 1);
        float c0 = __ldg(g_coef + j),     c1 = __ldg(g_coef + j + 1);
        float4 v0 = *reinterpret_cast<const float4*>(H + (size_t)s0 * 128 + lane * 4);
        float4 v1 = *reinterpret_cast<const float4*>(H + (size_t)s1 * 128 + lane * 4);
        a0.x = fmaf(c0, v0.x, a0.x); a0.y = fmaf(c0, v0.y, a0.y);
        a0.z = fmaf(c0, v0.z, a0.z); a0.w = fmaf(c0, v0.w, a0.w);
        a1.x = fmaf(c1, v1.x, a1.x); a1.y = fmaf(c1, v1.y, a1.y);
        a1.z = fmaf(c1, v1.z, a1.z); a1.w = fmaf(c1, v1.w, a1.w);
    }
    if (j < end) {
        int   s0 = __ldg(g_src  + j);
        float c0 = __ldg(g_coef + j);
        float4 v0 = *reinterpret_cast<const float4*>(H + (size_t)s0 * 128 + lane * 4);
        a0.x = fmaf(c0, v0.x, a0.x); a0.y = fmaf(c0, v0.y, a0.y);
        a0.z = fmaf(c0, v0.z, a0.z); a0.w = fmaf(c0, v0.w, a0.w);
    }
    a0.x += a1.x; a0.y += a1.y; a0.z += a1.z; a0.w += a1.w;
    *reinterpret_cast<float4*>(p) = a0;
}

// d=64: half-warp per node, lane -> float4
__global__ void k_gather64(const float* __restrict__ H, float* __restrict__ OUT, int N)
{
    int idx  = blockIdx.x * blockDim.x + threadIdx.x;
    int node = idx >> 4;
    int l    = idx & 15;
    if (node >= N) return;
    int beg = g_off[node], end = g_off[node + 1];
    float* p = OUT + (size_t)node * 64 + l * 4;
    float4 a0 = *reinterpret_cast<const float4*>(p);   // self-loop + bias (from GEMM)
    float4 a1 = make_float4(0.f, 0.f, 0.f, 0.f);
    int j = beg;
    for (; j + 1 < end; j += 2) {
        int   s0 = __ldg(g_src  + j),     s1 = __ldg(g_src  + j + 1);
        float c0 = __ldg(g_coef + j),     c1 = __ldg(g_coef + j + 1);
        float4 v0 = *reinterpret_cast<const float4*>(H + (size_t)s0 * 64 + l * 4);
        float4 v1 = *reinterpret_cast<const float4*>(H + (size_t)s1 * 64 + l * 4);
        a0.x = fmaf(c0, v0.x, a0.x); a0.y = fmaf(c0, v0.y, a0.y);
        a0.z = fmaf(c0, v0.z, a0.z); a0.w = fmaf(c0, v0.w, a0.w);
        a1.x = fmaf(c1, v1.x, a1.x); a1.y = fmaf(c1, v1.y, a1.y);
        a1.z = fmaf(c1, v1.z, a1.z); a1.w = fmaf(c1, v1.w, a1.w);
    }
    if (j < end) {
        int   s0 = __ldg(g_src  + j);
        float c0 = __ldg(g_coef + j);
        float4 v0 = *reinterpret_cast<const float4*>(H + (size_t)s0 * 64 + l * 4);
        a0.x = fmaf(c0, v0.x, a0.x); a0.y = fmaf(c0, v0.y, a0.y);
        a0.z = fmaf(c0, v0.z, a0.z); a0.w = fmaf(c0, v0.w, a0.w);
    }
    a0.x += a1.x; a0.y += a1.y; a0.z += a1.z; a0.w += a1.w;
    *reinterpret_cast<float4*>(p) = a0;
}

// ---------------------------------------------------------------------------
extern "C" void kernel_launch(void* const* d_in, const int* in_sizes, int n_in,
                              void* d_out, int out_size)
{
    const float* x  = (const float*)d_in[0];
    const int*   ei = (const int*)  d_in[1];
    const float* W1 = (const float*)d_in[2];
    const float* b1 = (const float*)d_in[3];
    const float* W2 = (const float*)d_in[4];
    const float* b2 = (const float*)d_in[5];
    float* out = (float*)d_out;

    const int N = in_sizes[0] / D0;   // 50000
    const int E = in_sizes[1] / 2;    // 625000

    float *p_h1, *p_agg1, *p_h2;
    cudaGetSymbolAddress((void**)&p_h1,   g_h1);
    cudaGetSymbolAddress((void**)&p_agg1, g_agg1);
    cudaGetSymbolAddress((void**)&p_h2,   g_h2);

    const int SMEM1 = (128 * (D1 + 4) + 128 * (128 + 4)) * 4;  // 135168 B
    const int SMEM2 = (128 * (D2 + 4) + 128 * (128 + 4)) * 4;  // 102400 B
    cudaFuncSetAttribute(k_gemm<D1, false, false>,
                         cudaFuncAttributeMaxDynamicSharedMemorySize, SMEM1);
    cudaFuncSetAttribute(k_gemm<D2, true, true>,
                         cudaFuncAttributeMaxDynamicSharedMemorySize, SMEM2);

    // 1. degree, dinv, CSR build
    k_zero_deg <<<(N + 255) / 256, 256>>>(N);
    k_count_deg<<<(E + 255) / 256, 256>>>(ei, E);
    k_dinv     <<<(N + 255) / 256, 256>>>(N);
    k_scan     <<<1, 1024>>>(N, E);
    k_fill     <<<(E + 255) / 256, 256>>>(ei, E);

    // 2. layer 1: h1 = x@W1^T ; agg1 = dinv^2*h1 ; gather neighbors
    k_gemm<D1, false, false><<<(N + 127) / 128, 256, SMEM1>>>(
        x, W1, nullptr, nullptr, p_h1, p_agg1, N);
    k_gather128<<<(N + 7) / 8, 256>>>(p_h1, p_agg1, N);

    // 3. layer 2: h2 = relu(agg1+b1)@W2^T ; out = dinv^2*h2 + b2 ; gather
    k_gemm<D2, true, true><<<(N + 127) / 128, 256, SMEM2>>>(
        p_agg1, W2, b1, b2, p_h2, out, N);
    k_gather64<<<(N * 16 + 255) / 256, 256>>>(p_h2, out, N);
}

// round 3
// speedup vs baseline: 1.2729x; 1.2729x over previous
#include <cuda_runtime.h>
#include <cstdint>

#define NN 50000
#define EE 625000
#define D0 128
#define D1 128
#define D2 64
#define SCAN_B 1024
#define NB ((NN + SCAN_B - 1) / SCAN_B)   // 49

// ---- device-global scratch (no allocation allowed) ----
__device__ int   g_degi[NN];
__device__ float g_dinv[NN];
__device__ int   g_off [NN + 1];
__device__ int   g_cur [NN];
__device__ int   g_src [EE];
__device__ float g_coef[EE];
__device__ int   g_bsum [NB];
__device__ int   g_bbase[NB];
__device__ float g_h1  [(size_t)NN * D1];
__device__ float g_agg1[(size_t)NN * D1];
__device__ float g_h2  [(size_t)NN * D2];

// ---------------------------------------------------------------------------
// Degree / normalization / CSR build
// ---------------------------------------------------------------------------
__global__ void k_zero_deg(int n) {
    int i = blockIdx.x * blockDim.x + threadIdx.x;
    if (i < n) g_degi[i] = 0;
}

__global__ void k_count_deg(const int* __restrict__ ei, int E) {
    int e = blockIdx.x * blockDim.x + threadIdx.x;
    if (e < E) atomicAdd(&g_degi[ei[E + e]], 1);
}

__global__ void k_dinv(int n) {
    int i = blockIdx.x * blockDim.x + threadIdx.x;
    if (i < n) g_dinv[i] = rsqrtf((float)(g_degi[i] + 1));   // +1 self-loop
}

// phase 1: per-block totals of g_degi
__global__ void k_blockreduce(int N) {
    __shared__ int warp_sum[32];
    int i = blockIdx.x * SCAN_B + threadIdx.x;
    int v = (i < N) ? g_degi[i] : 0;
    #pragma unroll
    for (int o = 16; o > 0; o >>= 1) v += __shfl_down_sync(0xffffffffu, v, o);
    if ((threadIdx.x & 31) == 0) warp_sum[threadIdx.x >> 5] = v;
    __syncthreads();
    if (threadIdx.x < 32) {
        int s = (threadIdx.x < (SCAN_B / 32)) ? warp_sum[threadIdx.x] : 0;
        #pragma unroll
        for (int o = 16; o > 0; o >>= 1) s += __shfl_down_sync(0xffffffffu, s, o);
        if (threadIdx.x == 0) g_bsum[blockIdx.x] = s;
    }
}

// phase 2: tiny serial scan of the 49 block sums
__global__ void k_scan_bsum(int B) {
    int acc = 0;
    for (int b = 0; b < B; b++) { g_bbase[b] = acc; acc += g_bsum[b]; }
}

// phase 3: per-block exclusive scan + base -> g_off, g_cur
__global__ void k_scan_final(int N, int E) {
    __shared__ int s[SCAN_B];
    int t = threadIdx.x;
    int i = blockIdx.x * SCAN_B + t;
    int v = (i < N) ? g_degi[i] : 0;
    s[t] = v;
    __syncthreads();
    #pragma unroll
    for (int off = 1; off < SCAN_B; off <<= 1) {
        int u = (t >= off) ? s[t - off] : 0;
        __syncthreads();
        s[t] += u;
        __syncthreads();
    }
    if (i < N) {
        int ex = g_bbase[blockIdx.x] + s[t] - v;   // exclusive
        g_off[i] = ex;
        g_cur[i] = ex;
        if (i == N - 1) g_off[N] = E;
    }
}

__global__ void k_fill(const int* __restrict__ ei, int E) {
    int e = blockIdx.x * blockDim.x + threadIdx.x;
    if (e >= E) return;
    int s = __ldg(ei + e);
    int d = __ldg(ei + E + e);
    int p = atomicAdd(&g_cur[d], 1);
    g_src[p]  = s;
    g_coef[p] = g_dinv[s] * g_dinv[d];
}

// ---------------------------------------------------------------------------
// Register-blocked fp32 GEMM: OUT[row][c] = sum_k A'[row][k] * W[c][k]
//   A' = relu(A + bin) if IN_ACT
//   H   <- acc ; AGG <- dinv[row]^2 * acc (+bout)
// 128x128 tile, 256 threads, 8 rows x (NG*4) cols per thread, xor-swizzled smem.
// ---------------------------------------------------------------------------
template <int NOUT, bool IN_ACT, bool OUT_BIAS>
__global__ __launch_bounds__(256, 1)
void k_gemm(const float* __restrict__ A, const float* __restrict__ W,
            const float* __restrict__ bin, const float* __restrict__ bout,
            float* __restrict__ H, float* __restrict__ AGG, int M)
{
    constexpr int K  = 128, TM = 128;
    constexpr int WS = NOUT + 4;
    constexpr int XS = TM + 4;
    constexpr int NG = NOUT / 64;
    constexpr int WM = NOUT / 4 - 1;
    constexpr int XM = TM / 4 - 1;

    extern __shared__ float sm[];
    float* Ws = sm;                    // [K][WS] swizzled
    float* Xs = sm + K * WS;           // [K][XS] swizzled

    const int tid  = threadIdx.x;
    const int row0 = blockIdx.x * TM;

    for (int fid = tid; fid < NOUT * (K / 4); fid += 256) {
        int c  = fid >> 5;
        int kq = fid & 31;
        float4 w = *reinterpret_cast<const float4*>(W + (size_t)c * K + kq * 4);
        float wr[4] = {w.x, w.y, w.z, w.w};
        #pragma unroll
        for (int u = 0; u < 4; u++) {
            int k = kq * 4 + u;
            Ws[k * WS + 4 * (((c >> 2) ^ (k & WM))) + (c & 3)] = wr[u];
        }
    }

    for (int fid = tid; fid < TM * (K / 4); fid += 256) {
        int r   = fid >> 5;
        int kq  = fid & 31;
        int row = row0 + r;
        float4 v = make_float4(0.f, 0.f, 0.f, 0.f);
        if (row < M)
            v = *reinterpret_cast<const float4*>(A + (size_t)row * K + kq * 4);
        if (IN_ACT) {
            v.x = fmaxf(v.x + __ldg(bin + kq * 4 + 0), 0.f);
            v.y = fmaxf(v.y + __ldg(bin + kq * 4 + 1), 0.f);
            v.z = fmaxf(v.z + __ldg(bin + kq * 4 + 2), 0.f);
            v.w = fmaxf(v.w + __ldg(bin + kq * 4 + 3), 0.f);
        }
        float xr[4] = {v.x, v.y, v.z, v.w};
        #pragma unroll
        for (int u = 0; u < 4; u++) {
            int k = kq * 4 + u;
            Xs[k * XS + 4 * (((r >> 2) ^ (k & XM))) + (r & 3)] = xr[u];
        }
    }
    __syncthreads();

    const int tx = tid & 15;
    const int ty = tid >> 4;

    float acc[2][4][NG][4];
    #pragma unroll
    for (int h = 0; h < 2; h++)
        #pragma unroll
        for (int i = 0; i < 4; i++)
            #pragma unroll
            for (int g = 0; g < NG; g++)
                #pragma unroll
                for (int j = 0; j < 4; j++) acc[h][i][g][j] = 0.f;

    #pragma unroll 4
    for (int k = 0; k < K; k++) {
        const int kx = k & XM;
        const int kw = k & WM;
        float4 xv[2];
        xv[0] = *reinterpret_cast<const float4*>(&Xs[k * XS + 4 * (ty ^ kx)]);
        xv[1] = *reinterpret_cast<const float4*>(&Xs[k * XS + 4 * ((ty + 16) ^ kx)]);
        float4 wv[NG];
        #pragma unroll
        for (int g = 0; g < NG; g++)
            wv[g] = *reinterpret_cast<const float4*>(&Ws[k * WS + 4 * ((tx + 16 * g) ^ kw)]);

        #pragma unroll
        for (int h = 0; h < 2; h++) {
            float xr[4] = {xv[h].x, xv[h].y, xv[h].z, xv[h].w};
            #pragma unroll
            for (int i = 0; i < 4; i++)
                #pragma unroll
                for (int g = 0; g < NG; g++) {
                    acc[h][i][g][0] = fmaf(xr[i], wv[g].x, acc[h][i][g][0]);
                    acc[h][i][g][1] = fmaf(xr[i], wv[g].y, acc[h][i][g][1]);
                    acc[h][i][g][2] = fmaf(xr[i], wv[g].z, acc[h][i][g][2]);
                    acc[h][i][g][3] = fmaf(xr[i], wv[g].w, acc[h][i][g][3]);
                }
        }
    }

    #pragma unroll
    for (int h = 0; h < 2; h++)
        #pragma unroll
        for (int i = 0; i < 4; i++) {
            int row = row0 + ty * 4 + h * 64 + i;
            if (row < M) {
                float s = g_dinv[row];
                s = s * s;
                #pragma unroll
                for (int g = 0; g < NG; g++) {
                    int c = tx * 4 + g * 64;
                    float4 hv = make_float4(acc[h][i][g][0], acc[h][i][g][1],
                                            acc[h][i][g][2], acc[h][i][g][3]);
                    *reinterpret_cast<float4*>(H + (size_t)row * NOUT + c) = hv;
                    float4 av;
                    if (OUT_BIAS) {
                        av.x = fmaf(s, hv.x, __ldg(bout + c + 0));
                        av.y = fmaf(s, hv.y, __ldg(bout + c + 1));
                        av.z = fmaf(s, hv.z, __ldg(bout + c + 2));
                        av.w = fmaf(s, hv.w, __ldg(bout + c + 3));
                    } else {
                        av = make_float4(s * hv.x, s * hv.y, s * hv.z, s * hv.w);
                    }
                    *reinterpret_cast<float4*>(AGG + (size_t)row * NOUT + c) = av;
                }
            }
        }
}

// ---------------------------------------------------------------------------
// CSR gather (no atomics)
// ---------------------------------------------------------------------------
__global__ void k_gather128(const float* __restrict__ H, float* __restrict__ AGG, int N)
{
    int node = blockIdx.x * (blockDim.x >> 5) + (threadIdx.x >> 5);
    int lane = threadIdx.x & 31;
    if (node >= N) return;
    int beg = g_off[node], end = g_off[node + 1];
    float* p = AGG + (size_t)node * 128 + lane * 4;
    float4 a0 = *reinterpret_cast<const float4*>(p);
    float4 a1 = make_float4(0.f, 0.f, 0.f, 0.f);
    int j = beg;
    for (; j + 1 < end; j += 2) {
        int   s0 = __ldg(g_src  + j),     s1 = __ldg(g_src  + j + 1);
        float c0 = __ldg(g_coef + j),     c1 = __ldg(g_coef + j + 1);
        float4 v0 = *reinterpret_cast<const float4*>(H + (size_t)s0 * 128 + lane * 4);
        float4 v1 = *reinterpret_cast<const float4*>(H + (size_t)s1 * 128 + lane * 4);
        a0.x = fmaf(c0, v0.x, a0.x); a0.y = fmaf(c0, v0.y, a0.y);
        a0.z = fmaf(c0, v0.z, a0.z); a0.w = fmaf(c0, v0.w, a0.w);
        a1.x = fmaf(c1, v1.x, a1.x); a1.y = fmaf(c1, v1.y, a1.y);
        a1.z = fmaf(c1, v1.z, a1.z); a1.w = fmaf(c1, v1.w, a1.w);
    }
    if (j < end) {
        int   s0 = __ldg(g_src  + j);
        float c0 = __ldg(g_coef + j);
        float4 v0 = *reinterpret_cast<const float4*>(H + (size_t)s0 * 128 + lane * 4);
        a0.x = fmaf(c0, v0.x, a0.x); a0.y = fmaf(c0, v0.y, a0.y);
        a0.z = fmaf(c0, v0.z, a0.z); a0.w = fmaf(c0, v0.w, a0.w);
    }
    a0.x += a1.x; a0.y += a1.y; a0.z += a1.z; a0.w += a1.w;
    *reinterpret_cast<float4*>(p) = a0;
}

__global__ void k_gather64(const float* __restrict__ H, float* __restrict__ OUT, int N)
{
    int idx  = blockIdx.x * blockDim.x + threadIdx.x;
    int node = idx >> 4;
    int l    = idx & 15;
    if (node >= N) return;
    int beg = g_off[node], end = g_off[node + 1];
    float* p = OUT + (size_t)node * 64 + l * 4;
    float4 a0 = *reinterpret_cast<const float4*>(p);
    float4 a1 = make_float4(0.f, 0.f, 0.f, 0.f);
    int j = beg;
    for (; j + 1 < end; j += 2) {
        int   s0 = __ldg(g_src  + j),     s1 = __ldg(g_src  + j + 1);
        float c0 = __ldg(g_coef + j),     c1 = __ldg(g_coef + j + 1);
        float4 v0 = *reinterpret_cast<const float4*>(H + (size_t)s0 * 64 + l * 4);
        float4 v1 = *reinterpret_cast<const float4*>(H + (size_t)s1 * 64 + l * 4);
        a0.x = fmaf(c0, v0.x, a0.x); a0.y = fmaf(c0, v0.y, a0.y);
        a0.z = fmaf(c0, v0.z, a0.z); a0.w = fmaf(c0, v0.w, a0.w);
        a1.x = fmaf(c1, v1.x, a1.x); a1.y = fmaf(c1, v1.y, a1.y);
        a1.z = fmaf(c1, v1.z, a1.z); a1.w = fmaf(c1, v1.w, a1.w);
    }
    if (j < end) {
        int   s0 = __ldg(g_src  + j);
        float c0 = __ldg(g_coef + j);
        float4 v0 = *reinterpret_cast<const float4*>(H + (size_t)s0 * 64 + l * 4);
        a0.x = fmaf(c0, v0.x, a0.x); a0.y = fmaf(c0, v0.y, a0.y);
        a0.z = fmaf(c0, v0.z, a0.z); a0.w = fmaf(c0, v0.w, a0.w);
    }
    a0.x += a1.x; a0.y += a1.y; a0.z += a1.z; a0.w += a1.w;
    *reinterpret_cast<float4*>(p) = a0;
}

// ---------------------------------------------------------------------------
extern "C" void kernel_launch(void* const* d_in, const int* in_sizes, int n_in,
                              void* d_out, int out_size)
{
    const float* x  = (const float*)d_in[0];
    const int*   ei = (const int*)  d_in[1];
    const float* W1 = (const float*)d_in[2];
    const float* b1 = (const float*)d_in[3];
    const float* W2 = (const float*)d_in[4];
    const float* b2 = (const float*)d_in[5];
    float* out = (float*)d_out;

    const int N = in_sizes[0] / D0;   // 50000
    const int E = in_sizes[1] / 2;    // 625000

    float *p_h1, *p_agg1, *p_h2;
    cudaGetSymbolAddress((void**)&p_h1,   g_h1);
    cudaGetSymbolAddress((void**)&p_agg1, g_agg1);
    cudaGetSymbolAddress((void**)&p_h2,   g_h2);

    const int SMEM1 = (128 * (D1 + 4) + 128 * (128 + 4)) * 4;
    const int SMEM2 = (128 * (D2 + 4) + 128 * (128 + 4)) * 4;
    cudaFuncSetAttribute(k_gemm<D1, false, false>,
                         cudaFuncAttributeMaxDynamicSharedMemorySize, SMEM1);
    cudaFuncSetAttribute(k_gemm<D2, true, true>,
                         cudaFuncAttributeMaxDynamicSharedMemorySize, SMEM2);

    const int nb = (N + SCAN_B - 1) / SCAN_B;

    // 1. degree, dinv, CSR build (parallel 3-phase scan)
    k_zero_deg   <<<(N + 255) / 256, 256>>>(N);
    k_count_deg  <<<(E + 255) / 256, 256>>>(ei, E);
    k_dinv       <<<(N + 255) / 256, 256>>>(N);
    k_blockreduce<<<nb, SCAN_B>>>(N);
    k_scan_bsum  <<<1, 1>>>(nb);
    k_scan_final <<<nb, SCAN_B>>>(N, E);
    k_fill       <<<(E + 255) / 256, 256>>>(ei, E);

    // 2. layer 1
    k_gemm<D1, false, false><<<(N + 127) / 128, 256, SMEM1>>>(
        x, W1, nullptr, nullptr, p_h1, p_agg1, N);
    k_gather128<<<(N + 7) / 8, 256>>>(p_h1, p_agg1, N);

    // 3. layer 2
    k_gemm<D2, true, true><<<(N + 127) / 128, 256, SMEM2>>>(
        p_agg1, W2, b1, b2, p_h2, out, N);
    k_gather64<<<(N * 16 + 255) / 256, 256>>>(p_h2, out, N);
}

// round 5
// speedup vs baseline: 1.9147x; 1.5042x over previous
#include <cuda_runtime.h>
#include <cuda_bf16.h>
#include <cstdint>

#define NN 50000
#define EE 625000
#define D0 128
#define D1 128
#define D2 64
#define SCAN_B 1024
#define NB ((NN + SCAN_B - 1) / SCAN_B)

// ---- device-global scratch ----
__device__ int   g_degi[NN];
__device__ float g_dinv[NN];
__device__ int   g_off [NN + 1];
__device__ int   g_cur [NN];
__device__ int   g_src [EE];
__device__ float g_coef[EE];
__device__ int   g_bsum [NB];
__device__ int   g_bbase[NB];
__device__ float g_h1  [(size_t)NN * D1];
__device__ float g_agg1[(size_t)NN * D1];
__device__ float g_h2  [(size_t)NN * D2];

// ---------------------------------------------------------------------------
// Warp MMA helpers (sm_80+ PTX: works on plain sm_103 target)
// ---------------------------------------------------------------------------
__device__ __forceinline__ uint32_t smem_u32(const void* p) {
    uint32_t a;
    asm("{ .reg .u64 t; cvta.to.shared.u64 t, %1; cvt.u32.u64 %0, t; }" : "=r"(a) : "l"(p));
    return a;
}
__device__ __forceinline__ void ldsm_x4(uint32_t* r, uint32_t addr) {
    asm volatile("ldmatrix.sync.aligned.m8n8.x4.shared.b16 {%0,%1,%2,%3}, [%4];"
                 : "=r"(r[0]), "=r"(r[1]), "=r"(r[2]), "=r"(r[3]) : "r"(addr));
}
__device__ __forceinline__ void mma_bf16(float* d, const uint32_t* a, const uint32_t* b) {
    asm volatile(
        "mma.sync.aligned.m16n8k16.row.col.f32.bf16.bf16.f32 "
        "{%0,%1,%2,%3}, {%4,%5,%6,%7}, {%8,%9}, {%0,%1,%2,%3};"
        : "+f"(d[0]), "+f"(d[1]), "+f"(d[2]), "+f"(d[3])
        : "r"(a[0]), "r"(a[1]), "r"(a[2]), "r"(a[3]), "r"(b[0]), "r"(b[1]));
}

// ---------------------------------------------------------------------------
// CSR build kernels (unchanged from R3)
// ---------------------------------------------------------------------------
__global__ void k_zero_deg(int n) {
    int i = blockIdx.x * blockDim.x + threadIdx.x;
    if (i < n) g_degi[i] = 0;
}
__global__ void k_count_deg(const int* __restrict__ ei, int E) {
    int e = blockIdx.x * blockDim.x + threadIdx.x;
    if (e < E) atomicAdd(&g_degi[ei[E + e]], 1);
}
__global__ void k_dinv(int n) {
    int i = blockIdx.x * blockDim.x + threadIdx.x;
    if (i < n) g_dinv[i] = rsqrtf((float)(g_degi[i] + 1));
}
__global__ void k_blockreduce(int N) {
    __shared__ int warp_sum[32];
    int i = blockIdx.x * SCAN_B + threadIdx.x;
    int v = (i < N) ? g_degi[i] : 0;
    #pragma unroll
    for (int o = 16; o > 0; o >>= 1) v += __shfl_down_sync(0xffffffffu, v, o);
    if ((threadIdx.x & 31) == 0) warp_sum[threadIdx.x >> 5] = v;
    __syncthreads();
    if (threadIdx.x < 32) {
        int s = (threadIdx.x < (SCAN_B / 32)) ? warp_sum[threadIdx.x] : 0;
        #pragma unroll
        for (int o = 16; o > 0; o >>= 1) s += __shfl_down_sync(0xffffffffu, s, o);
        if (threadIdx.x == 0) g_bsum[blockIdx.x] = s;
    }
}
__global__ void k_scan_bsum(int B) {
    int acc = 0;
    for (int b = 0; b < B; b++) { g_bbase[b] = acc; acc += g_bsum[b]; }
}
__global__ void k_scan_final(int N, int E) {
    __shared__ int s[SCAN_B];
    int t = threadIdx.x;
    int i = blockIdx.x * SCAN_B + t;
    int v = (i < N) ? g_degi[i] : 0;
    s[t] = v;
    __syncthreads();
    #pragma unroll
    for (int off = 1; off < SCAN_B; off <<= 1) {
        int u = (t >= off) ? s[t - off] : 0;
        __syncthreads();
        s[t] += u;
        __syncthreads();
    }
    if (i < N) {
        int ex = g_bbase[blockIdx.x] + s[t] - v;
        g_off[i] = ex;
        g_cur[i] = ex;
        if (i == N - 1) g_off[N] = E;
    }
}
__global__ void k_fill(const int* __restrict__ ei, int E) {
    int e = blockIdx.x * blockDim.x + threadIdx.x;
    if (e >= E) return;
    int s = __ldg(ei + e);
    int d = __ldg(ei + E + e);
    int p = atomicAdd(&g_cur[d], 1);
    g_src[p]  = s;
    g_coef[p] = g_dinv[s] * g_dinv[d];
}

// ---------------------------------------------------------------------------
// Tensor-core GEMM via mma.sync bf16 hi/lo split (fp32 accumulate):
//   acc = Ahi@Whi^T + Ahi@Wlo^T + Alo@Whi^T
//   A' = relu(A + bin) if IN_ACT; H <- acc ; AGG <- dinv[row]^2*acc (+bout)
// Tile 128 x NOUT x K=128; 8 warps, each 32 rows x NOUT/2 cols.
// smem tiles bf16, row stride K+8 (272 B) -> conflict-free ldmatrix.
// ---------------------------------------------------------------------------
template <int NOUT, bool IN_ACT, bool OUT_BIAS>
__global__ __launch_bounds__(256, 1)
void k_mma_gemm(const float* __restrict__ A, const float* __restrict__ W,
                const float* __restrict__ bin, const float* __restrict__ bout,
                float* __restrict__ H, float* __restrict__ AGG, int M)
{
    constexpr int K   = 128, TM = 128;
    constexpr int LDB = (K + 8) * 2;               // row stride in bytes (272)
    constexpr uint32_t OFF_AHI = 0;
    constexpr uint32_t OFF_ALO = OFF_AHI + TM * LDB;
    constexpr uint32_t OFF_WHI = OFF_ALO + TM * LDB;
    constexpr uint32_t OFF_WLO = OFF_WHI + NOUT * LDB;
    constexpr int WN = NOUT / 2;                   // cols per warp
    constexpr int NT = NOUT / 16;                  // n8-tiles per warp
    constexpr int NG = NT / 2;                     // ldmatrix.x4 groups (B)

    extern __shared__ char smem[];
    const uint32_t sb = smem_u32(smem);
    const int tid    = threadIdx.x;
    const int wid    = tid >> 5;
    const int lane   = tid & 31;
    const int warp_m = wid & 3;
    const int warp_n = wid >> 2;
    const int row0   = blockIdx.x * TM;

    // ---- convert A tile -> bf16 hi/lo
    for (int fid = tid; fid < TM * (K / 4); fid += 256) {
        int r = fid >> 5, k = (fid & 31) * 4;
        int row = row0 + r;
        float4 v = make_float4(0.f, 0.f, 0.f, 0.f);
        if (row < M)
            v = *reinterpret_cast<const float4*>(A + (size_t)row * K + k);
        if (IN_ACT) {
            v.x = fmaxf(v.x + __ldg(bin + k + 0), 0.f);
            v.y = fmaxf(v.y + __ldg(bin + k + 1), 0.f);
            v.z = fmaxf(v.z + __ldg(bin + k + 2), 0.f);
            v.w = fmaxf(v.w + __ldg(bin + k + 3), 0.f);
        }
        __nv_bfloat162 h01, h23, l01, l23;
        h01.x = __float2bfloat16_rn(v.x); h01.y = __float2bfloat16_rn(v.y);
        h23.x = __float2bfloat16_rn(v.z); h23.y = __float2bfloat16_rn(v.w);
        l01.x = __float2bfloat16_rn(v.x - __bfloat162float(h01.x));
        l01.y = __float2bfloat16_rn(v.y - __bfloat162float(h01.y));
        l23.x = __float2bfloat16_rn(v.z - __bfloat162float(h23.x));
        l23.y = __float2bfloat16_rn(v.w - __bfloat162float(h23.y));
        uint32_t o = (uint32_t)r * LDB + (uint32_t)k * 2;
        *reinterpret_cast<uint2*>(smem + OFF_AHI + o) =
            make_uint2(*reinterpret_cast<uint32_t*>(&h01), *reinterpret_cast<uint32_t*>(&h23));
        *reinterpret_cast<uint2*>(smem + OFF_ALO + o) =
            make_uint2(*reinterpret_cast<uint32_t*>(&l01), *reinterpret_cast<uint32_t*>(&l23));
    }
    // ---- convert W -> bf16 hi/lo (W is [NOUT][K] row-major == col-major B)
    for (int fid = tid; fid < NOUT * (K / 4); fid += 256) {
        int c = fid >> 5, k = (fid & 31) * 4;
        float4 v = *reinterpret_cast<const float4*>(W + (size_t)c * K + k);
        __nv_bfloat162 h01, h23, l01, l23;
        h01.x = __float2bfloat16_rn(v.x); h01.y = __float2bfloat16_rn(v.y);
        h23.x = __float2bfloat16_rn(v.z); h23.y = __float2bfloat16_rn(v.w);
        l01.x = __float2bfloat16_rn(v.x - __bfloat162float(h01.x));
        l01.y = __float2bfloat16_rn(v.y - __bfloat162float(h01.y));
        l23.x = __float2bfloat16_rn(v.z - __bfloat162float(h23.x));
        l23.y = __float2bfloat16_rn(v.w - __bfloat162float(h23.y));
        uint32_t o = (uint32_t)c * LDB + (uint32_t)k * 2;
        *reinterpret_cast<uint2*>(smem + OFF_WHI + o) =
            make_uint2(*reinterpret_cast<uint32_t*>(&h01), *reinterpret_cast<uint32_t*>(&h23));
        *reinterpret_cast<uint2*>(smem + OFF_WLO + o) =
            make_uint2(*reinterpret_cast<uint32_t*>(&l01), *reinterpret_cast<uint32_t*>(&l23));
    }
    __syncthreads();

    float acc[2][NT][4];
    #pragma unroll
    for (int mt = 0; mt < 2; mt++)
        #pragma unroll
        for (int nt = 0; nt < NT; nt++)
            #pragma unroll
            for (int j = 0; j < 4; j++) acc[mt][nt][j] = 0.f;

    // A-fragment lane addressing: row = base + (lane&7) + ((lane>>3)&1)*8,
    //                             col = k0 + (lane>>4)*8
    const uint32_t a_roff = (uint32_t)((lane & 7) + ((lane >> 3) & 1) * 8) * LDB
                          + (uint32_t)((lane >> 4) * 8) * 2;
    // B-fragment lane addressing: row(n) = base + (lane&7) + ((lane>>4)&1)*8,
    //                             col = k0 + ((lane>>3)&1)*8
    const uint32_t b_roff = (uint32_t)((lane & 7) + ((lane >> 4) & 1) * 8) * LDB
                          + (uint32_t)(((lane >> 3) & 1) * 8) * 2;

    #pragma unroll
    for (int ks = 0; ks < K / 16; ks++) {
        const uint32_t kb = (uint32_t)(ks * 16) * 2;
        uint32_t ah[2][4], al[2][4];
        #pragma unroll
        for (int mt = 0; mt < 2; mt++) {
            uint32_t base = (uint32_t)(warp_m * 32 + mt * 16) * LDB + kb + a_roff;
            ldsm_x4(ah[mt], sb + OFF_AHI + base);
            ldsm_x4(al[mt], sb + OFF_ALO + base);
        }
        uint32_t bh[NG][4], bl[NG][4];
        #pragma unroll
        for (int g = 0; g < NG; g++) {
            uint32_t base = (uint32_t)(warp_n * WN + g * 16) * LDB + kb + b_roff;
            ldsm_x4(bh[g], sb + OFF_WHI + base);
            ldsm_x4(bl[g], sb + OFF_WLO + base);
        }
        #pragma unroll
        for (int mt = 0; mt < 2; mt++)
            #pragma unroll
            for (int nt = 0; nt < NT; nt++) {
                const uint32_t* ph = &bh[nt >> 1][(nt & 1) * 2];
                const uint32_t* pl = &bl[nt >> 1][(nt & 1) * 2];
                mma_bf16(acc[mt][nt], ah[mt], ph);   // hi*hi
                mma_bf16(acc[mt][nt], ah[mt], pl);   // hi*lo
                mma_bf16(acc[mt][nt], al[mt], ph);   // lo*hi
            }
    }

    // ---- epilogue: H = acc ; AGG = dinv^2*acc (+bout)
    #pragma unroll
    for (int mt = 0; mt < 2; mt++) {
        int rbase = row0 + warp_m * 32 + mt * 16 + (lane >> 2);
        #pragma unroll
        for (int hf = 0; hf < 2; hf++) {
            int row = rbase + hf * 8;
            if (row < M) {
                float s = g_dinv[row];
                s = s * s;
                #pragma unroll
                for (int nt = 0; nt < NT; nt++) {
                    int c = warp_n * WN + nt * 8 + (lane & 3) * 2;
                    float2 hv = make_float2(acc[mt][nt][hf * 2 + 0], acc[mt][nt][hf * 2 + 1]);
                    *reinterpret_cast<float2*>(H + (size_t)row * NOUT + c) = hv;
                    float2 av;
                    if (OUT_BIAS) {
                        av.x = fmaf(s, hv.x, __ldg(bout + c + 0));
                        av.y = fmaf(s, hv.y, __ldg(bout + c + 1));
                    } else {
                        av = make_float2(s * hv.x, s * hv.y);
                    }
                    *reinterpret_cast<float2*>(AGG + (size_t)row * NOUT + c) = av;
                }
            }
        }
    }
}

// ---------------------------------------------------------------------------
// CSR gather (unchanged from R3)
// ---------------------------------------------------------------------------
__global__ void k_gather128(const float* __restrict__ H, float* __restrict__ AGG, int N)
{
    int node = blockIdx.x * (blockDim.x >> 5) + (threadIdx.x >> 5);
    int lane = threadIdx.x & 31;
    if (node >= N) return;
    int beg = g_off[node], end = g_off[node + 1];
    float* p = AGG + (size_t)node * 128 + lane * 4;
    float4 a0 = *reinterpret_cast<const float4*>(p);
    float4 a1 = make_float4(0.f, 0.f, 0.f, 0.f);
    int j = beg;
    for (; j + 1 < end; j += 2) {
        int   s0 = __ldg(g_src  + j),     s1 = __ldg(g_src  + j + 1);
        float c0 = __ldg(g_coef + j),     c1 = __ldg(g_coef + j + 1);
        float4 v0 = *reinterpret_cast<const float4*>(H + (size_t)s0 * 128 + lane * 4);
        float4 v1 = *reinterpret_cast<const float4*>(H + (size_t)s1 * 128 + lane * 4);
        a0.x = fmaf(c0, v0.x, a0.x); a0.y = fmaf(c0, v0.y, a0.y);
        a0.z = fmaf(c0, v0.z, a0.z); a0.w = fmaf(c0, v0.w, a0.w);
        a1.x = fmaf(c1, v1.x, a1.x); a1.y = fmaf(c1, v1.y, a1.y);
        a1.z = fmaf(c1, v1.z, a1.z); a1.w = fmaf(c1, v1.w, a1.w);
    }
    if (j < end) {
        int   s0 = __ldg(g_src  + j);
        float c0 = __ldg(g_coef + j);
        float4 v0 = *reinterpret_cast<const float4*>(H + (size_t)s0 * 128 + lane * 4);
        a0.x = fmaf(c0, v0.x, a0.x); a0.y = fmaf(c0, v0.y, a0.y);
        a0.z = fmaf(c0, v0.z, a0.z); a0.w = fmaf(c0, v0.w, a0.w);
    }
    a0.x += a1.x; a0.y += a1.y; a0.z += a1.z; a0.w += a1.w;
    *reinterpret_cast<float4*>(p) = a0;
}

__global__ void k_gather64(const float* __restrict__ H, float* __restrict__ OUT, int N)
{
    int idx  = blockIdx.x * blockDim.x + threadIdx.x;
    int node = idx >> 4;
    int l    = idx & 15;
    if (node >= N) return;
    int beg = g_off[node], end = g_off[node + 1];
    float* p = OUT + (size_t)node * 64 + l * 4;
    float4 a0 = *reinterpret_cast<const float4*>(p);
    float4 a1 = make_float4(0.f, 0.f, 0.f, 0.f);
    int j = beg;
    for (; j + 1 < end; j += 2) {
        int   s0 = __ldg(g_src  + j),     s1 = __ldg(g_src  + j + 1);
        float c0 = __ldg(g_coef + j),     c1 = __ldg(g_coef + j + 1);
        float4 v0 = *reinterpret_cast<const float4*>(H + (size_t)s0 * 64 + l * 4);
        float4 v1 = *reinterpret_cast<const float4*>(H + (size_t)s1 * 64 + l * 4);
        a0.x = fmaf(c0, v0.x, a0.x); a0.y = fmaf(c0, v0.y, a0.y);
        a0.z = fmaf(c0, v0.z, a0.z); a0.w = fmaf(c0, v0.w, a0.w);
        a1.x = fmaf(c1, v1.x, a1.x); a1.y = fmaf(c1, v1.y, a1.y);
        a1.z = fmaf(c1, v1.z, a1.z); a1.w = fmaf(c1, v1.w, a1.w);
    }
    if (j < end) {
        int   s0 = __ldg(g_src  + j);
        float c0 = __ldg(g_coef + j);
        float4 v0 = *reinterpret_cast<const float4*>(H + (size_t)s0 * 64 + l * 4);
        a0.x = fmaf(c0, v0.x, a0.x); a0.y = fmaf(c0, v0.y, a0.y);
        a0.z = fmaf(c0, v0.z, a0.z); a0.w = fmaf(c0, v0.w, a0.w);
    }
    a0.x += a1.x; a0.y += a1.y; a0.z += a1.z; a0.w += a1.w;
    *reinterpret_cast<float4*>(p) = a0;
}

// ---------------------------------------------------------------------------
extern "C" void kernel_launch(void* const* d_in, const int* in_sizes, int n_in,
                              void* d_out, int out_size)
{
    const float* x  = (const float*)d_in[0];
    const int*   ei = (const int*)  d_in[1];
    const float* W1 = (const float*)d_in[2];
    const float* b1 = (const float*)d_in[3];
    const float* W2 = (const float*)d_in[4];
    const float* b2 = (const float*)d_in[5];
    float* out = (float*)d_out;

    const int N = in_sizes[0] / D0;   // 50000
    const int E = in_sizes[1] / 2;    // 625000

    float *p_h1, *p_agg1, *p_h2;
    cudaGetSymbolAddress((void**)&p_h1,   g_h1);
    cudaGetSymbolAddress((void**)&p_agg1, g_agg1);
    cudaGetSymbolAddress((void**)&p_h2,   g_h2);

    const int LDBB  = (128 + 8) * 2;
    const int SMEM1 = (128 + 128 + D1 + D1) * LDBB;   // 139264 B
    const int SMEM2 = (128 + 128 + D2 + D2) * LDBB;   // 104448 B
    cudaFuncSetAttribute(k_mma_gemm<D1, false, false>,
                         cudaFuncAttributeMaxDynamicSharedMemorySize, SMEM1);
    cudaFuncSetAttribute(k_mma_gemm<D2, true, true>,
                         cudaFuncAttributeMaxDynamicSharedMemorySize, SMEM2);

    const int nb = (N + SCAN_B - 1) / SCAN_B;

    // 1. degree, dinv, CSR build
    k_zero_deg   <<<(N + 255) / 256, 256>>>(N);
    k_count_deg  <<<(E + 255) / 256, 256>>>(ei, E);
    k_dinv       <<<(N + 255) / 256, 256>>>(N);
    k_blockreduce<<<nb, SCAN_B>>>(N);
    k_scan_bsum  <<<1, 1>>>(nb);
    k_scan_final <<<nb, SCAN_B>>>(N, E);
    k_fill       <<<(E + 255) / 256, 256>>>(ei, E);

    // 2. layer 1: h1 = x@W1^T (HMMA) ; agg1 = dinv^2*h1 ; gather
    k_mma_gemm<D1, false, false><<<(N + 127) / 128, 256, SMEM1>>>(
        x, W1, nullptr, nullptr, p_h1, p_agg1, N);
    k_gather128<<<(N + 7) / 8, 256>>>(p_h1, p_agg1, N);

    // 3. layer 2: h2 = relu(agg1+b1)@W2^T ; out = dinv^2*h2 + b2 ; gather
    k_mma_gemm<D2, true, true><<<(N + 127) / 128, 256, SMEM2>>>(
        p_agg1, W2, b1, b2, p_h2, out, N);
    k_gather64<<<(N * 16 + 255) / 256, 256>>>(p_h2, out, N);
}

// round 6
// speedup vs baseline: 2.1568x; 1.1264x over previous
#include <cuda_runtime.h>
#include <cuda_bf16.h>
#include <cstdint>

#define NN 50000
#define EE 625000
#define D0 128
#define D1 128
#define D2 64
#define SCAN_B 1024
#define NB ((NN + SCAN_B - 1) / SCAN_B)

// ---- device-global scratch ----
__device__ int   g_degi[NN];
__device__ float g_dinv[NN];
__device__ int   g_off [NN + 1];
__device__ int   g_cur [NN];
__device__ int2  g_edge[EE];          // packed (src, coef bits)
__device__ int   g_bsum [NB];
__device__ int   g_bbase[NB];
__device__ float g_h1  [(size_t)NN * D1];
__device__ float g_agg1[(size_t)NN * D1];
__device__ float g_h2  [(size_t)NN * D2];

// ---------------------------------------------------------------------------
// Warp MMA helpers (sm_80+ PTX)
// ---------------------------------------------------------------------------
__device__ __forceinline__ uint32_t smem_u32(const void* p) {
    uint32_t a;
    asm("{ .reg .u64 t; cvta.to.shared.u64 t, %1; cvt.u32.u64 %0, t; }" : "=r"(a) : "l"(p));
    return a;
}
__device__ __forceinline__ void ldsm_x4(uint32_t* r, uint32_t addr) {
    asm volatile("ldmatrix.sync.aligned.m8n8.x4.shared.b16 {%0,%1,%2,%3}, [%4];"
                 : "=r"(r[0]), "=r"(r[1]), "=r"(r[2]), "=r"(r[3]) : "r"(addr));
}
__device__ __forceinline__ void mma_bf16(float* d, const uint32_t* a, const uint32_t* b) {
    asm volatile(
        "mma.sync.aligned.m16n8k16.row.col.f32.bf16.bf16.f32 "
        "{%0,%1,%2,%3}, {%4,%5,%6,%7}, {%8,%9}, {%0,%1,%2,%3};"
        : "+f"(d[0]), "+f"(d[1]), "+f"(d[2]), "+f"(d[3])
        : "r"(a[0]), "r"(a[1]), "r"(a[2]), "r"(a[3]), "r"(b[0]), "r"(b[1]));
}

// ---------------------------------------------------------------------------
// CSR build
// ---------------------------------------------------------------------------
__global__ void k_count_deg(const int* __restrict__ ei, int E) {
    int e = blockIdx.x * blockDim.x + threadIdx.x;
    if (e < E) atomicAdd(&g_degi[ei[E + e]], 1);
}

// fused: dinv[i] = rsqrt(deg+1)  AND  per-block sums of deg -> g_bsum
__global__ void k_dinv_blockreduce(int N) {
    __shared__ int warp_sum[32];
    int i = blockIdx.x * SCAN_B + threadIdx.x;
    int v = 0;
    if (i < N) {
        v = g_degi[i];
        g_dinv[i] = rsqrtf((float)(v + 1));
    }
    int s = v;
    #pragma unroll
    for (int o = 16; o > 0; o >>= 1) s += __shfl_down_sync(0xffffffffu, s, o);
    if ((threadIdx.x & 31) == 0) warp_sum[threadIdx.x >> 5] = s;
    __syncthreads();
    if (threadIdx.x < 32) {
        int t = (threadIdx.x < (SCAN_B / 32)) ? warp_sum[threadIdx.x] : 0;
        #pragma unroll
        for (int o = 16; o > 0; o >>= 1) t += __shfl_down_sync(0xffffffffu, t, o);
        if (threadIdx.x == 0) g_bsum[blockIdx.x] = t;
    }
}
__global__ void k_scan_bsum(int B) {
    int acc = 0;
    for (int b = 0; b < B; b++) { g_bbase[b] = acc; acc += g_bsum[b]; }
}
__global__ void k_scan_final(int N, int E) {
    __shared__ int s[SCAN_B];
    int t = threadIdx.x;
    int i = blockIdx.x * SCAN_B + t;
    int v = (i < N) ? g_degi[i] : 0;
    s[t] = v;
    __syncthreads();
    #pragma unroll
    for (int off = 1; off < SCAN_B; off <<= 1) {
        int u = (t >= off) ? s[t - off] : 0;
        __syncthreads();
        s[t] += u;
        __syncthreads();
    }
    if (i < N) {
        int ex = g_bbase[blockIdx.x] + s[t] - v;
        g_off[i] = ex;
        g_cur[i] = ex;
        if (i == N - 1) g_off[N] = E;
    }
}
__global__ void k_fill(const int* __restrict__ ei, int E) {
    int e = blockIdx.x * blockDim.x + threadIdx.x;
    if (e >= E) return;
    int s = __ldg(ei + e);
    int d = __ldg(ei + E + e);
    int p = atomicAdd(&g_cur[d], 1);
    g_edge[p] = make_int2(s, __float_as_int(g_dinv[s] * g_dinv[d]));
}

// ---------------------------------------------------------------------------
// Tensor-core GEMM (bf16 hi/lo split, fp32 acc).
//   H <- acc always; if WRITE_AGG: AGG <- dinv^2*acc (+bout)
// ---------------------------------------------------------------------------
template <int NOUT, bool IN_ACT, bool OUT_BIAS, bool WRITE_AGG>
__global__ __launch_bounds__(256, 1)
void k_mma_gemm(const float* __restrict__ A, const float* __restrict__ W,
                const float* __restrict__ bin, const float* __restrict__ bout,
                float* __restrict__ H, float* __restrict__ AGG, int M)
{
    constexpr int K   = 128, TM = 128;
    constexpr int LDB = (K + 8) * 2;
    constexpr uint32_t OFF_AHI = 0;
    constexpr uint32_t OFF_ALO = OFF_AHI + TM * LDB;
    constexpr uint32_t OFF_WHI = OFF_ALO + TM * LDB;
    constexpr uint32_t OFF_WLO = OFF_WHI + NOUT * LDB;
    constexpr int WN = NOUT / 2;
    constexpr int NT = NOUT / 16;
    constexpr int NG = NT / 2;

    extern __shared__ char smem[];
    const uint32_t sb = smem_u32(smem);
    const int tid    = threadIdx.x;
    const int wid    = tid >> 5;
    const int lane   = tid & 31;
    const int warp_m = wid & 3;
    const int warp_n = wid >> 2;
    const int row0   = blockIdx.x * TM;

    for (int fid = tid; fid < TM * (K / 4); fid += 256) {
        int r = fid >> 5, k = (fid & 31) * 4;
        int row = row0 + r;
        float4 v = make_float4(0.f, 0.f, 0.f, 0.f);
        if (row < M)
            v = *reinterpret_cast<const float4*>(A + (size_t)row * K + k);
        if (IN_ACT) {
            v.x = fmaxf(v.x + __ldg(bin + k + 0), 0.f);
            v.y = fmaxf(v.y + __ldg(bin + k + 1), 0.f);
            v.z = fmaxf(v.z + __ldg(bin + k + 2), 0.f);
            v.w = fmaxf(v.w + __ldg(bin + k + 3), 0.f);
        }
        __nv_bfloat162 h01, h23, l01, l23;
        h01.x = __float2bfloat16_rn(v.x); h01.y = __float2bfloat16_rn(v.y);
        h23.x = __float2bfloat16_rn(v.z); h23.y = __float2bfloat16_rn(v.w);
        l01.x = __float2bfloat16_rn(v.x - __bfloat162float(h01.x));
        l01.y = __float2bfloat16_rn(v.y - __bfloat162float(h01.y));
        l23.x = __float2bfloat16_rn(v.z - __bfloat162float(h23.x));
        l23.y = __float2bfloat16_rn(v.w - __bfloat162float(h23.y));
        uint32_t o = (uint32_t)r * LDB + (uint32_t)k * 2;
        *reinterpret_cast<uint2*>(smem + OFF_AHI + o) =
            make_uint2(*reinterpret_cast<uint32_t*>(&h01), *reinterpret_cast<uint32_t*>(&h23));
        *reinterpret_cast<uint2*>(smem + OFF_ALO + o) =
            make_uint2(*reinterpret_cast<uint32_t*>(&l01), *reinterpret_cast<uint32_t*>(&l23));
    }
    for (int fid = tid; fid < NOUT * (K / 4); fid += 256) {
        int c = fid >> 5, k = (fid & 31) * 4;
        float4 v = *reinterpret_cast<const float4*>(W + (size_t)c * K + k);
        __nv_bfloat162 h01, h23, l01, l23;
        h01.x = __float2bfloat16_rn(v.x); h01.y = __float2bfloat16_rn(v.y);
        h23.x = __float2bfloat16_rn(v.z); h23.y = __float2bfloat16_rn(v.w);
        l01.x = __float2bfloat16_rn(v.x - __bfloat162float(h01.x));
        l01.y = __float2bfloat16_rn(v.y - __bfloat162float(h01.y));
        l23.x = __float2bfloat16_rn(v.z - __bfloat162float(h23.x));
        l23.y = __float2bfloat16_rn(v.w - __bfloat162float(h23.y));
        uint32_t o = (uint32_t)c * LDB + (uint32_t)k * 2;
        *reinterpret_cast<uint2*>(smem + OFF_WHI + o) =
            make_uint2(*reinterpret_cast<uint32_t*>(&h01), *reinterpret_cast<uint32_t*>(&h23));
        *reinterpret_cast<uint2*>(smem + OFF_WLO + o) =
            make_uint2(*reinterpret_cast<uint32_t*>(&l01), *reinterpret_cast<uint32_t*>(&l23));
    }
    __syncthreads();

    float acc[2][NT][4];
    #pragma unroll
    for (int mt = 0; mt < 2; mt++)
        #pragma unroll
        for (int nt = 0; nt < NT; nt++)
            #pragma unroll
            for (int j = 0; j < 4; j++) acc[mt][nt][j] = 0.f;

    const uint32_t a_roff = (uint32_t)((lane & 7) + ((lane >> 3) & 1) * 8) * LDB
                          + (uint32_t)((lane >> 4) * 8) * 2;
    const uint32_t b_roff = (uint32_t)((lane & 7) + ((lane >> 4) & 1) * 8) * LDB
                          + (uint32_t)(((lane >> 3) & 1) * 8) * 2;

    #pragma unroll
    for (int ks = 0; ks < K / 16; ks++) {
        const uint32_t kb = (uint32_t)(ks * 16) * 2;
        uint32_t ah[2][4], al[2][4];
        #pragma unroll
        for (int mt = 0; mt < 2; mt++) {
            uint32_t base = (uint32_t)(warp_m * 32 + mt * 16) * LDB + kb + a_roff;
            ldsm_x4(ah[mt], sb + OFF_AHI + base);
            ldsm_x4(al[mt], sb + OFF_ALO + base);
        }
        uint32_t bh[NG][4], bl[NG][4];
        #pragma unroll
        for (int g = 0; g < NG; g++) {
            uint32_t base = (uint32_t)(warp_n * WN + g * 16) * LDB + kb + b_roff;
            ldsm_x4(bh[g], sb + OFF_WHI + base);
            ldsm_x4(bl[g], sb + OFF_WLO + base);
        }
        #pragma unroll
        for (int mt = 0; mt < 2; mt++)
            #pragma unroll
            for (int nt = 0; nt < NT; nt++) {
                const uint32_t* ph = &bh[nt >> 1][(nt & 1) * 2];
                const uint32_t* pl = &bl[nt >> 1][(nt & 1) * 2];
                mma_bf16(acc[mt][nt], ah[mt], ph);
                mma_bf16(acc[mt][nt], ah[mt], pl);
                mma_bf16(acc[mt][nt], al[mt], ph);
            }
    }

    #pragma unroll
    for (int mt = 0; mt < 2; mt++) {
        int rbase = row0 + warp_m * 32 + mt * 16 + (lane >> 2);
        #pragma unroll
        for (int hf = 0; hf < 2; hf++) {
            int row = rbase + hf * 8;
            if (row < M) {
                float s = 0.f;
                if (WRITE_AGG) { s = g_dinv[row]; s = s * s; }
                #pragma unroll
                for (int nt = 0; nt < NT; nt++) {
                    int c = warp_n * WN + nt * 8 + (lane & 3) * 2;
                    float2 hv = make_float2(acc[mt][nt][hf * 2 + 0], acc[mt][nt][hf * 2 + 1]);
                    *reinterpret_cast<float2*>(H + (size_t)row * NOUT + c) = hv;
                    if (WRITE_AGG) {
                        float2 av;
                        if (OUT_BIAS) {
                            av.x = fmaf(s, hv.x, __ldg(bout + c + 0));
                            av.y = fmaf(s, hv.y, __ldg(bout + c + 1));
                        } else {
                            av = make_float2(s * hv.x, s * hv.y);
                        }
                        *reinterpret_cast<float2*>(AGG + (size_t)row * NOUT + c) = av;
                    }
                }
            }
        }
    }
}

// ---------------------------------------------------------------------------
// CSR gather, packed edges, unroll 4.
// gather128 also adds the self-loop term dinv^2 * H[node].
// ---------------------------------------------------------------------------
#define EDGE_FMA(a, e, width)                                                     \
    {                                                                             \
        float c_ = __int_as_float((e).y);                                         \
        const float4 v_ = *reinterpret_cast<const float4*>(                       \
            H + (size_t)(e).x * (width) + lane4);                                 \
        (a).x = fmaf(c_, v_.x, (a).x); (a).y = fmaf(c_, v_.y, (a).y);             \
        (a).z = fmaf(c_, v_.z, (a).z); (a).w = fmaf(c_, v_.w, (a).w);             \
    }

__global__ void k_gather128(const float* __restrict__ H, float* __restrict__ AGG, int N)
{
    int node = blockIdx.x * (blockDim.x >> 5) + (threadIdx.x >> 5);
    int lane4 = (threadIdx.x & 31) * 4;
    if (node >= N) return;
    int beg = g_off[node], end = g_off[node + 1];
    float s = g_dinv[node]; s = s * s;
    float4 hs = *reinterpret_cast<const float4*>(H + (size_t)node * 128 + lane4);
    float4 a0 = make_float4(s * hs.x, s * hs.y, s * hs.z, s * hs.w);
    float4 a1 = make_float4(0.f, 0.f, 0.f, 0.f);
    float4 a2 = make_float4(0.f, 0.f, 0.f, 0.f);
    float4 a3 = make_float4(0.f, 0.f, 0.f, 0.f);
    int j = beg;
    for (; j + 3 < end; j += 4) {
        int2 e0 = __ldg(&g_edge[j + 0]);
        int2 e1 = __ldg(&g_edge[j + 1]);
        int2 e2 = __ldg(&g_edge[j + 2]);
        int2 e3 = __ldg(&g_edge[j + 3]);
        EDGE_FMA(a0, e0, 128) EDGE_FMA(a1, e1, 128)
        EDGE_FMA(a2, e2, 128) EDGE_FMA(a3, e3, 128)
    }
    for (; j < end; j++) {
        int2 e0 = __ldg(&g_edge[j]);
        EDGE_FMA(a0, e0, 128)
    }
    a0.x += a1.x + a2.x + a3.x; a0.y += a1.y + a2.y + a3.y;
    a0.z += a1.z + a2.z + a3.z; a0.w += a1.w + a2.w + a3.w;
    *reinterpret_cast<float4*>(AGG + (size_t)node * 128 + lane4) = a0;
}

__global__ void k_gather64(const float* __restrict__ H, float* __restrict__ OUT, int N)
{
    int idx  = blockIdx.x * blockDim.x + threadIdx.x;
    int node = idx >> 4;
    int lane4 = (idx & 15) * 4;
    if (node >= N) return;
    int beg = g_off[node], end = g_off[node + 1];
    float* p = OUT + (size_t)node * 64 + lane4;
    float4 a0 = *reinterpret_cast<const float4*>(p);   // dinv^2*h2 + b2 from gemm2
    float4 a1 = make_float4(0.f, 0.f, 0.f, 0.f);
    float4 a2 = make_float4(0.f, 0.f, 0.f, 0.f);
    float4 a3 = make_float4(0.f, 0.f, 0.f, 0.f);
    int j = beg;
    for (; j + 3 < end; j += 4) {
        int2 e0 = __ldg(&g_edge[j + 0]);
        int2 e1 = __ldg(&g_edge[j + 1]);
        int2 e2 = __ldg(&g_edge[j + 2]);
        int2 e3 = __ldg(&g_edge[j + 3]);
        EDGE_FMA(a0, e0, 64) EDGE_FMA(a1, e1, 64)
        EDGE_FMA(a2, e2, 64) EDGE_FMA(a3, e3, 64)
    }
    for (; j < end; j++) {
        int2 e0 = __ldg(&g_edge[j]);
        EDGE_FMA(a0, e0, 64)
    }
    a0.x += a1.x + a2.x + a3.x; a0.y += a1.y + a2.y + a3.y;
    a0.z += a1.z + a2.z + a3.z; a0.w += a1.w + a2.w + a3.w;
    *reinterpret_cast<float4*>(p) = a0;
}

// ---------------------------------------------------------------------------
extern "C" void kernel_launch(void* const* d_in, const int* in_sizes, int n_in,
                              void* d_out, int out_size)
{
    const float* x  = (const float*)d_in[0];
    const int*   ei = (const int*)  d_in[1];
    const float* W1 = (const float*)d_in[2];
    const float* b1 = (const float*)d_in[3];
    const float* W2 = (const float*)d_in[4];
    const float* b2 = (const float*)d_in[5];
    float* out = (float*)d_out;

    const int N = in_sizes[0] / D0;
    const int E = in_sizes[1] / 2;

    float *p_h1, *p_agg1, *p_h2;
    int   *p_degi;
    cudaGetSymbolAddress((void**)&p_h1,   g_h1);
    cudaGetSymbolAddress((void**)&p_agg1, g_agg1);
    cudaGetSymbolAddress((void**)&p_h2,   g_h2);
    cudaGetSymbolAddress((void**)&p_degi, g_degi);

    const int LDBB  = (128 + 8) * 2;
    const int SMEM1 = (128 + 128 + D1 + D1) * LDBB;
    const int SMEM2 = (128 + 128 + D2 + D2) * LDBB;
    cudaFuncSetAttribute(k_mma_gemm<D1, false, false, false>,
                         cudaFuncAttributeMaxDynamicSharedMemorySize, SMEM1);
    cudaFuncSetAttribute(k_mma_gemm<D2, true, true, true>,
                         cudaFuncAttributeMaxDynamicSharedMemorySize, SMEM2);

    const int nb = (N + SCAN_B - 1) / SCAN_B;

    // ---- fork: branch B (CSR build) runs concurrently with gemm1 on branch A
    cudaStream_t s2;
    cudaStreamCreate(&s2);
    cudaEvent_t evF, evJ;
    cudaEventCreateWithFlags(&evF, cudaEventDisableTiming);
    cudaEventCreateWithFlags(&evJ, cudaEventDisableTiming);

    cudaEventRecord(evF, 0);
    cudaStreamWaitEvent(s2, evF, 0);

    // branch B (stream s2): degree -> dinv -> scan -> fill
    cudaMemsetAsync(p_degi, 0, (size_t)N * sizeof(int), s2);
    k_count_deg       <<<(E + 255) / 256, 256, 0, s2>>>(ei, E);
    k_dinv_blockreduce<<<nb, SCAN_B, 0, s2>>>(N);
    k_scan_bsum       <<<1, 1, 0, s2>>>(nb);
    k_scan_final      <<<nb, SCAN_B, 0, s2>>>(N, E);
    k_fill            <<<(E + 255) / 256, 256, 0, s2>>>(ei, E);
    cudaEventRecord(evJ, s2);

    // branch A (stream 0): pure GEMM1 (writes h1 only, no dinv dependency)
    k_mma_gemm<D1, false, false, false><<<(N + 127) / 128, 256, SMEM1, 0>>>(
        x, W1, nullptr, nullptr, p_h1, nullptr, N);

    // join
    cudaStreamWaitEvent(0, evJ, 0);

    // gather128: agg1 = dinv^2*h1[self] + sum coef*h1[src]
    k_gather128<<<(N + 7) / 8, 256, 0, 0>>>(p_h1, p_agg1, N);

    // gemm2: h2 = relu(agg1+b1)@W2^T ; out = dinv^2*h2 + b2
    k_mma_gemm<D2, true, true, true><<<(N + 127) / 128, 256, SMEM2, 0>>>(
        p_agg1, W2, b1, b2, p_h2, out, N);
    k_gather64<<<(N * 16 + 255) / 256, 256, 0, 0>>>(p_h2, out, N);

    cudaStreamDestroy(s2);
    cudaEventDestroy(evF);
    cudaEventDestroy(evJ);
}

// round 7
// speedup vs baseline: 2.2892x; 1.0614x over previous
#include <cuda_runtime.h>
#include <cuda_bf16.h>
#include <cstdint>

#define NN 50000
#define EE 625000
#define D0 128
#define D1 128
#define D2 64
#define SCAN_B 1024
#define NB ((NN + SCAN_B - 1) / SCAN_B)

// ---- device-global scratch ----
__device__ int   g_degi[NN];
__device__ float g_dinv[NN];
__device__ int   g_off [NN + 1];
__device__ int   g_cur [NN];
__device__ int2  g_edge[EE];
__device__ int   g_bsum [NB];
__device__ int   g_bbase[NB];
__device__ float g_h1  [(size_t)NN * D1];
__device__ float g_agg1[(size_t)NN * D1];
__device__ float g_h2  [(size_t)NN * D2];

// ---------------------------------------------------------------------------
// Warp MMA helpers
// ---------------------------------------------------------------------------
__device__ __forceinline__ uint32_t smem_u32(const void* p) {
    uint32_t a;
    asm("{ .reg .u64 t; cvta.to.shared.u64 t, %1; cvt.u32.u64 %0, t; }" : "=r"(a) : "l"(p));
    return a;
}
__device__ __forceinline__ void ldsm_x4(uint32_t* r, uint32_t addr) {
    asm volatile("ldmatrix.sync.aligned.m8n8.x4.shared.b16 {%0,%1,%2,%3}, [%4];"
                 : "=r"(r[0]), "=r"(r[1]), "=r"(r[2]), "=r"(r[3]) : "r"(addr));
}
__device__ __forceinline__ void mma_bf16(float* d, const uint32_t* a, const uint32_t* b) {
    asm volatile(
        "mma.sync.aligned.m16n8k16.row.col.f32.bf16.bf16.f32 "
        "{%0,%1,%2,%3}, {%4,%5,%6,%7}, {%8,%9}, {%0,%1,%2,%3};"
        : "+f"(d[0]), "+f"(d[1]), "+f"(d[2]), "+f"(d[3])
        : "r"(a[0]), "r"(a[1]), "r"(a[2]), "r"(a[3]), "r"(b[0]), "r"(b[1]));
}

// ---------------------------------------------------------------------------
// CSR build
// ---------------------------------------------------------------------------
__global__ void k_count_deg(const int* __restrict__ ei, int E) {
    int e = blockIdx.x * blockDim.x + threadIdx.x;
    if (e < E) atomicAdd(&g_degi[ei[E + e]], 1);
}

__global__ void k_dinv_blockreduce(int N) {
    __shared__ int warp_sum[32];
    int i = blockIdx.x * SCAN_B + threadIdx.x;
    int v = 0;
    if (i < N) {
        v = g_degi[i];
        g_dinv[i] = rsqrtf((float)(v + 1));
    }
    int s = v;
    #pragma unroll
    for (int o = 16; o > 0; o >>= 1) s += __shfl_down_sync(0xffffffffu, s, o);
    if ((threadIdx.x & 31) == 0) warp_sum[threadIdx.x >> 5] = s;
    __syncthreads();
    if (threadIdx.x < 32) {
        int t = (threadIdx.x < (SCAN_B / 32)) ? warp_sum[threadIdx.x] : 0;
        #pragma unroll
        for (int o = 16; o > 0; o >>= 1) t += __shfl_down_sync(0xffffffffu, t, o);
        if (threadIdx.x == 0) g_bsum[blockIdx.x] = t;
    }
}

// one-warp shfl scan of the <=64 block sums (was 1-thread serial chain)
__global__ void k_scan_bsum(int B) {
    int lane = threadIdx.x;
    int i0 = 2 * lane, i1 = 2 * lane + 1;
    int v0 = (i0 < B) ? g_bsum[i0] : 0;
    int v1 = (i1 < B) ? g_bsum[i1] : 0;
    int p = v0 + v1;
    int s = p;
    #pragma unroll
    for (int o = 1; o < 32; o <<= 1) {
        int u = __shfl_up_sync(0xffffffffu, s, o);
        if (lane >= o) s += u;
    }
    int ex = s - p;
    if (i0 < B) g_bbase[i0] = ex;
    if (i1 < B) g_bbase[i1] = ex + v0;
}

__global__ void k_scan_final(int N, int E) {
    __shared__ int s[SCAN_B];
    int t = threadIdx.x;
    int i = blockIdx.x * SCAN_B + t;
    int v = (i < N) ? g_degi[i] : 0;
    s[t] = v;
    __syncthreads();
    #pragma unroll
    for (int off = 1; off < SCAN_B; off <<= 1) {
        int u = (t >= off) ? s[t - off] : 0;
        __syncthreads();
        s[t] += u;
        __syncthreads();
    }
    if (i < N) {
        int ex = g_bbase[blockIdx.x] + s[t] - v;
        g_off[i] = ex;
        g_cur[i] = ex;
        if (i == N - 1) g_off[N] = E;
    }
}
__global__ void k_fill(const int* __restrict__ ei, int E) {
    int e = blockIdx.x * blockDim.x + threadIdx.x;
    if (e >= E) return;
    int s = __ldg(ei + e);
    int d = __ldg(ei + E + e);
    int p = atomicAdd(&g_cur[d], 1);
    g_edge[p] = make_int2(s, __float_as_int(g_dinv[s] * g_dinv[d]));
}

// ---------------------------------------------------------------------------
// Tensor-core GEMM (bf16 hi/lo split, fp32 acc), occupancy 2.
// TM in {64,128}; 8 warps = MW x NW grid (MW = TM/32).
// row_base: absolute row offset (chunked launches) for g_dinv indexing.
// ---------------------------------------------------------------------------
template <int TM, int NOUT, bool IN_ACT, bool OUT_BIAS, bool WRITE_AGG>
__global__ __launch_bounds__(256, 2)
void k_mma_gemm(const float* __restrict__ A, const float* __restrict__ W,
                const float* __restrict__ bin, const float* __restrict__ bout,
                float* __restrict__ H, float* __restrict__ AGG, int M, int row_base)
{
    constexpr int K   = 128;
    constexpr int LDB = (K + 8) * 2;
    constexpr uint32_t OFF_AHI = 0;
    constexpr uint32_t OFF_ALO = OFF_AHI + TM * LDB;
    constexpr uint32_t OFF_WHI = OFF_ALO + TM * LDB;
    constexpr uint32_t OFF_WLO = OFF_WHI + NOUT * LDB;
    constexpr int MW = TM / 32;        // m-warps
    constexpr int NW = 8 / MW;         // n-warps
    constexpr int WN = NOUT / NW;      // cols per warp (32)
    constexpr int NT = WN / 8;         // n8 tiles per warp (4)
    constexpr int NG = NT / 2;         // ldmatrix.x4 groups (2)

    extern __shared__ char smem[];
    const uint32_t sb = smem_u32(smem);
    const int tid    = threadIdx.x;
    const int wid    = tid >> 5;
    const int lane   = tid & 31;
    const int warp_m = wid & (MW - 1);
    const int warp_n = wid / MW;
    const int row0   = blockIdx.x * TM;

    for (int fid = tid; fid < TM * (K / 4); fid += 256) {
        int r = fid >> 5, k = (fid & 31) * 4;
        int row = row0 + r;
        float4 v = make_float4(0.f, 0.f, 0.f, 0.f);
        if (row < M)
            v = *reinterpret_cast<const float4*>(A + (size_t)row * K + k);
        if (IN_ACT) {
            v.x = fmaxf(v.x + __ldg(bin + k + 0), 0.f);
            v.y = fmaxf(v.y + __ldg(bin + k + 1), 0.f);
            v.z = fmaxf(v.z + __ldg(bin + k + 2), 0.f);
            v.w = fmaxf(v.w + __ldg(bin + k + 3), 0.f);
        }
        __nv_bfloat162 h01, h23, l01, l23;
        h01.x = __float2bfloat16_rn(v.x); h01.y = __float2bfloat16_rn(v.y);
        h23.x = __float2bfloat16_rn(v.z); h23.y = __float2bfloat16_rn(v.w);
        l01.x = __float2bfloat16_rn(v.x - __bfloat162float(h01.x));
        l01.y = __float2bfloat16_rn(v.y - __bfloat162float(h01.y));
        l23.x = __float2bfloat16_rn(v.z - __bfloat162float(h23.x));
        l23.y = __float2bfloat16_rn(v.w - __bfloat162float(h23.y));
        uint32_t o = (uint32_t)r * LDB + (uint32_t)k * 2;
        *reinterpret_cast<uint2*>(smem + OFF_AHI + o) =
            make_uint2(*reinterpret_cast<uint32_t*>(&h01), *reinterpret_cast<uint32_t*>(&h23));
        *reinterpret_cast<uint2*>(smem + OFF_ALO + o) =
            make_uint2(*reinterpret_cast<uint32_t*>(&l01), *reinterpret_cast<uint32_t*>(&l23));
    }
    for (int fid = tid; fid < NOUT * (K / 4); fid += 256) {
        int c = fid >> 5, k = (fid & 31) * 4;
        float4 v = *reinterpret_cast<const float4*>(W + (size_t)c * K + k);
        __nv_bfloat162 h01, h23, l01, l23;
        h01.x = __float2bfloat16_rn(v.x); h01.y = __float2bfloat16_rn(v.y);
        h23.x = __float2bfloat16_rn(v.z); h23.y = __float2bfloat16_rn(v.w);
        l01.x = __float2bfloat16_rn(v.x - __bfloat162float(h01.x));
        l01.y = __float2bfloat16_rn(v.y - __bfloat162float(h01.y));
        l23.x = __float2bfloat16_rn(v.z - __bfloat162float(h23.x));
        l23.y = __float2bfloat16_rn(v.w - __bfloat162float(h23.y));
        uint32_t o = (uint32_t)c * LDB + (uint32_t)k * 2;
        *reinterpret_cast<uint2*>(smem + OFF_WHI + o) =
            make_uint2(*reinterpret_cast<uint32_t*>(&h01), *reinterpret_cast<uint32_t*>(&h23));
        *reinterpret_cast<uint2*>(smem + OFF_WLO + o) =
            make_uint2(*reinterpret_cast<uint32_t*>(&l01), *reinterpret_cast<uint32_t*>(&l23));
    }
    __syncthreads();

    float acc[2][NT][4];
    #pragma unroll
    for (int mt = 0; mt < 2; mt++)
        #pragma unroll
        for (int nt = 0; nt < NT; nt++)
            #pragma unroll
            for (int j = 0; j < 4; j++) acc[mt][nt][j] = 0.f;

    const uint32_t a_roff = (uint32_t)((lane & 7) + ((lane >> 3) & 1) * 8) * LDB
                          + (uint32_t)((lane >> 4) * 8) * 2;
    const uint32_t b_roff = (uint32_t)((lane & 7) + ((lane >> 4) & 1) * 8) * LDB
                          + (uint32_t)(((lane >> 3) & 1) * 8) * 2;

    #pragma unroll
    for (int ks = 0; ks < K / 16; ks++) {
        const uint32_t kb = (uint32_t)(ks * 16) * 2;
        uint32_t ah[2][4], al[2][4];
        #pragma unroll
        for (int mt = 0; mt < 2; mt++) {
            uint32_t base = (uint32_t)(warp_m * 32 + mt * 16) * LDB + kb + a_roff;
            ldsm_x4(ah[mt], sb + OFF_AHI + base);
            ldsm_x4(al[mt], sb + OFF_ALO + base);
        }
        uint32_t bh[NG][4], bl[NG][4];
        #pragma unroll
        for (int g = 0; g < NG; g++) {
            uint32_t base = (uint32_t)(warp_n * WN + g * 16) * LDB + kb + b_roff;
            ldsm_x4(bh[g], sb + OFF_WHI + base);
            ldsm_x4(bl[g], sb + OFF_WLO + base);
        }
        #pragma unroll
        for (int mt = 0; mt < 2; mt++)
            #pragma unroll
            for (int nt = 0; nt < NT; nt++) {
                const uint32_t* ph = &bh[nt >> 1][(nt & 1) * 2];
                const uint32_t* pl = &bl[nt >> 1][(nt & 1) * 2];
                mma_bf16(acc[mt][nt], ah[mt], ph);
                mma_bf16(acc[mt][nt], ah[mt], pl);
                mma_bf16(acc[mt][nt], al[mt], ph);
            }
    }

    #pragma unroll
    for (int mt = 0; mt < 2; mt++) {
        int rbase = row0 + warp_m * 32 + mt * 16 + (lane >> 2);
        #pragma unroll
        for (int hf = 0; hf < 2; hf++) {
            int row = rbase + hf * 8;
            if (row < M) {
                float s = 0.f;
                if (WRITE_AGG) { s = g_dinv[row_base + row]; s = s * s; }
                #pragma unroll
                for (int nt = 0; nt < NT; nt++) {
                    int c = warp_n * WN + nt * 8 + (lane & 3) * 2;
                    float2 hv = make_float2(acc[mt][nt][hf * 2 + 0], acc[mt][nt][hf * 2 + 1]);
                    *reinterpret_cast<float2*>(H + (size_t)row * NOUT + c) = hv;
                    if (WRITE_AGG) {
                        float2 av;
                        if (OUT_BIAS) {
                            av.x = fmaf(s, hv.x, __ldg(bout + c + 0));
                            av.y = fmaf(s, hv.y, __ldg(bout + c + 1));
                        } else {
                            av = make_float2(s * hv.x, s * hv.y);
                        }
                        *reinterpret_cast<float2*>(AGG + (size_t)row * NOUT + c) = av;
                    }
                }
            }
        }
    }
}

// ---------------------------------------------------------------------------
// CSR gathers (chunked on node range)
// ---------------------------------------------------------------------------
#define EDGE_FMA(a, e, width)                                                     \
    {                                                                             \
        float c_ = __int_as_float((e).y);                                         \
        const float4 v_ = *reinterpret_cast<const float4*>(                       \
            H + (size_t)(e).x * (width) + lane4);                                 \
        (a).x = fmaf(c_, v_.x, (a).x); (a).y = fmaf(c_, v_.y, (a).y);             \
        (a).z = fmaf(c_, v_.z, (a).z); (a).w = fmaf(c_, v_.w, (a).w);             \
    }

__global__ void k_gather128(const float* __restrict__ H, float* __restrict__ AGG,
                            int node_beg, int node_end)
{
    int node = node_beg + blockIdx.x * (blockDim.x >> 5) + (threadIdx.x >> 5);
    int lane4 = (threadIdx.x & 31) * 4;
    if (node >= node_end) return;
    int beg = g_off[node], end = g_off[node + 1];
    float s = g_dinv[node]; s = s * s;
    float4 hs = *reinterpret_cast<const float4*>(H + (size_t)node * 128 + lane4);
    float4 a0 = make_float4(s * hs.x, s * hs.y, s * hs.z, s * hs.w);
    float4 a1 = make_float4(0.f, 0.f, 0.f, 0.f);
    float4 a2 = make_float4(0.f, 0.f, 0.f, 0.f);
    float4 a3 = make_float4(0.f, 0.f, 0.f, 0.f);
    int j = beg;
    for (; j + 3 < end; j += 4) {
        int2 e0 = __ldg(&g_edge[j + 0]);
        int2 e1 = __ldg(&g_edge[j + 1]);
        int2 e2 = __ldg(&g_edge[j + 2]);
        int2 e3 = __ldg(&g_edge[j + 3]);
        EDGE_FMA(a0, e0, 128) EDGE_FMA(a1, e1, 128)
        EDGE_FMA(a2, e2, 128) EDGE_FMA(a3, e3, 128)
    }
    for (; j < end; j++) {
        int2 e0 = __ldg(&g_edge[j]);
        EDGE_FMA(a0, e0, 128)
    }
    a0.x += a1.x + a2.x + a3.x; a0.y += a1.y + a2.y + a3.y;
    a0.z += a1.z + a2.z + a3.z; a0.w += a1.w + a2.w + a3.w;
    *reinterpret_cast<float4*>(AGG + (size_t)node * 128 + lane4) = a0;
}

__global__ void k_gather64(const float* __restrict__ H, float* __restrict__ OUT, int N)
{
    int idx  = blockIdx.x * blockDim.x + threadIdx.x;
    int node = idx >> 4;
    int lane4 = (idx & 15) * 4;
    if (node >= N) return;
    int beg = g_off[node], end = g_off[node + 1];
    float* p = OUT + (size_t)node * 64 + lane4;
    float4 a0 = *reinterpret_cast<const float4*>(p);
    float4 a1 = make_float4(0.f, 0.f, 0.f, 0.f);
    float4 a2 = make_float4(0.f, 0.f, 0.f, 0.f);
    float4 a3 = make_float4(0.f, 0.f, 0.f, 0.f);
    int j = beg;
    for (; j + 3 < end; j += 4) {
        int2 e0 = __ldg(&g_edge[j + 0]);
        int2 e1 = __ldg(&g_edge[j + 1]);
        int2 e2 = __ldg(&g_edge[j + 2]);
        int2 e3 = __ldg(&g_edge[j + 3]);
        EDGE_FMA(a0, e0, 64) EDGE_FMA(a1, e1, 64)
        EDGE_FMA(a2, e2, 64) EDGE_FMA(a3, e3, 64)
    }
    for (; j < end; j++) {
        int2 e0 = __ldg(&g_edge[j]);
        EDGE_FMA(a0, e0, 64)
    }
    a0.x += a1.x + a2.x + a3.x; a0.y += a1.y + a2.y + a3.y;
    a0.z += a1.z + a2.z + a3.z; a0.w += a1.w + a2.w + a3.w;
    *reinterpret_cast<float4*>(p) = a0;
}

// ---------------------------------------------------------------------------
extern "C" void kernel_launch(void* const* d_in, const int* in_sizes, int n_in,
                              void* d_out, int out_size)
{
    const float* x  = (const float*)d_in[0];
    const int*   ei = (const int*)  d_in[1];
    const float* W1 = (const float*)d_in[2];
    const float* b1 = (const float*)d_in[3];
    const float* W2 = (const float*)d_in[4];
    const float* b2 = (const float*)d_in[5];
    float* out = (float*)d_out;

    const int N = in_sizes[0] / D0;
    const int E = in_sizes[1] / 2;

    float *p_h1, *p_agg1, *p_h2;
    int   *p_degi;
    cudaGetSymbolAddress((void**)&p_h1,   g_h1);
    cudaGetSymbolAddress((void**)&p_agg1, g_agg1);
    cudaGetSymbolAddress((void**)&p_h2,   g_h2);
    cudaGetSymbolAddress((void**)&p_degi, g_degi);

    const int LDBB  = (128 + 8) * 2;
    const int SMEM1 = (64 + 64 + D1 + D1) * LDBB;     // 104448 (TM=64)
    const int SMEM2 = (128 + 128 + D2 + D2) * LDBB;   // 104448 (TM=128)
    cudaFuncSetAttribute(k_mma_gemm<64, D1, false, false, false>,
                         cudaFuncAttributeMaxDynamicSharedMemorySize, SMEM1);
    cudaFuncSetAttribute(k_mma_gemm<128, D2, true, true, true>,
                         cudaFuncAttributeMaxDynamicSharedMemorySize, SMEM2);

    const int nb = (N + SCAN_B - 1) / SCAN_B;

    cudaStream_t s2;
    cudaStreamCreate(&s2);
    cudaEvent_t evF, evCSR, evG1, evB;
    cudaEventCreateWithFlags(&evF,   cudaEventDisableTiming);
    cudaEventCreateWithFlags(&evCSR, cudaEventDisableTiming);
    cudaEventCreateWithFlags(&evG1,  cudaEventDisableTiming);
    cudaEventCreateWithFlags(&evB,   cudaEventDisableTiming);

    cudaEventRecord(evF, 0);
    cudaStreamWaitEvent(s2, evF, 0);

    // branch B (s2): CSR build
    cudaMemsetAsync(p_degi, 0, (size_t)N * sizeof(int), s2);
    k_count_deg       <<<(E + 255) / 256, 256, 0, s2>>>(ei, E);
    k_dinv_blockreduce<<<nb, SCAN_B, 0, s2>>>(N);
    k_scan_bsum       <<<1, 32, 0, s2>>>(nb);
    k_scan_final      <<<nb, SCAN_B, 0, s2>>>(N, E);
    k_fill            <<<(E + 255) / 256, 256, 0, s2>>>(ei, E);
    cudaEventRecord(evCSR, s2);

    // branch A (stream 0): pure GEMM1 (TM=64, occupancy 2)
    k_mma_gemm<64, D1, false, false, false><<<(N + 63) / 64, 256, SMEM1, 0>>>(
        x, W1, nullptr, nullptr, p_h1, nullptr, N, 0);
    cudaEventRecord(evG1, 0);

    // join both ways for the chunked tail
    cudaStreamWaitEvent(0, evCSR, 0);
    cudaStreamWaitEvent(s2, evG1, 0);

    // chunked tail: chunk0 on stream 0, chunk1 on s2
    const int half  = (N + 1) / 2;
    const int n0    = half, n1 = N - half;

    k_gather128<<<(n0 + 7) / 8, 256, 0, 0>>>(p_h1, p_agg1, 0, n0);
    k_mma_gemm<128, D2, true, true, true><<<(n0 + 127) / 128, 256, SMEM2, 0>>>(
        p_agg1, W2, b1, b2, p_h2, out, n0, 0);

    k_gather128<<<(n1 + 7) / 8, 256, 0, s2>>>(p_h1, p_agg1, n0, N);
    k_mma_gemm<128, D2, true, true, true><<<(n1 + 127) / 128, 256, SMEM2, s2>>>(
        p_agg1 + (size_t)n0 * D1, W2, b1, b2,
        p_h2 + (size_t)n0 * D2, out + (size_t)n0 * D2, n1, n0);
    cudaEventRecord(evB, s2);

    cudaStreamWaitEvent(0, evB, 0);
    k_gather64<<<(N * 16 + 255) / 256, 256, 0, 0>>>(p_h2, out, N);

    cudaStreamDestroy(s2);
    cudaEventDestroy(evF);
    cudaEventDestroy(evCSR);
    cudaEventDestroy(evG1);
    cudaEventDestroy(evB);
}